// round 3
// baseline (speedup 1.0000x reference)
#include <cuda_runtime.h>

// Shapes (fixed for this problem)
#define Bb 8
#define Nn 1024
#define BN 8192          // B*N points
#define Fdim 128         // feature dim
#define Hh 4
#define Kk 32
#define HK 128           // H*K keys
#define FOUT 128
#define TP 64            // points per block
#define NBLK (BN/TP)     // 128 blocks

// smem strides (floats)
#define KS 132           // keysT row stride (2-way conflict on transpose store, cf reads)
#define XS 68            // xT row stride
#define TSs 132          // tS row stride (float4-aligned)

#define OUT_ELEMS (Bb*Kk*FOUT)      // 32768

// Scratch (no allocation allowed -> device global)
__device__ float g_part[NBLK * Kk * Fdim];   // [blk][k][f] partial pooled

// ---------------------------------------------------------------------------
// Kernel A: L1 distance (min-sum identity) + student-t + per-head normalize
// + head-conv + softmax over K + partial attention-pooling. One launch.
// Grid: 128 blocks x 1024 threads, ~142KB dynamic smem (1 block/SM, 32 warps).
// ---------------------------------------------------------------------------
__global__ __launch_bounds__(1024, 1) void distS_kernel(
    const float* __restrict__ x, const float* __restrict__ keys,
    const float* __restrict__ convw, float* __restrict__ Sg)
{
    extern __shared__ float sm[];
    float* keysT = sm;                    // [128][KS]  keys transposed [f][k]
    float* xT    = keysT + Fdim * KS;     // [128][XS]  x tile transposed [f][p]
    float* tS    = xT + Fdim * XS;        // [TP][TSs]  t values, then S
    float* redK  = tS + TP * TSs;         // [8][128]
    float* redX  = redK + 8 * HK;         // [16][64]
    float* ksum  = redX + 16 * TP;        // [128]
    float* xsum  = ksum + HK;             // [64]
    float* cw    = xsum + TP;             // [4] (+pad)

    const int tid = threadIdx.x;
    const int p0  = blockIdx.x * TP;

    if (tid < Hh) cw[tid] = convw[tid];

    // ---- keys transpose (float4 coalesced reads, 2-way-conflict stores) ----
    {
        const float4* k4 = (const float4*)keys;
        #pragma unroll
        for (int it = 0; it < 4; it++) {
            int i4 = tid + it * 1024;         // 4096 float4 total
            int k  = i4 >> 5;
            int f4 = i4 & 31;
            float4 v = k4[i4];
            keysT[(f4 * 4 + 0) * KS + k] = v.x;
            keysT[(f4 * 4 + 1) * KS + k] = v.y;
            keysT[(f4 * 4 + 2) * KS + k] = v.z;
            keysT[(f4 * 4 + 3) * KS + k] = v.w;
        }
    }
    // ---- x tile transpose (float4 reads) ----
    {
        const float4* x4 = (const float4*)(x + (size_t)p0 * Fdim);
        #pragma unroll
        for (int it = 0; it < 2; it++) {
            int i4 = tid + it * 1024;         // 2048 float4 total
            int p  = i4 >> 5;
            int f4 = i4 & 31;
            float4 v = x4[i4];
            xT[(f4 * 4 + 0) * XS + p] = v.x;
            xT[(f4 * 4 + 1) * XS + p] = v.y;
            xT[(f4 * 4 + 2) * XS + p] = v.z;
            xT[(f4 * 4 + 3) * XS + p] = v.w;
        }
    }
    __syncthreads();

    // ---- row sums (parallel 2-level): d = ksum[k] + xsum[p] - 2*minsum ----
    {
        int k = tid & 127, part = tid >> 7;            // 8 f-parts x 128 k
        float s = 0.f;
        #pragma unroll
        for (int i = 0; i < 16; i++) s += keysT[(part * 16 + i) * KS + k];
        redK[part * HK + k] = s;
    }
    {
        int p = tid & 63, part = tid >> 6;             // 16 f-parts x 64 p
        float s = 0.f;
        #pragma unroll
        for (int i = 0; i < 8; i++) s += xT[(part * 8 + i) * XS + p];
        redX[part * TP + p] = s;
    }
    __syncthreads();
    if (tid < HK) {
        float s = 0.f;
        #pragma unroll
        for (int r = 0; r < 8; r++) s += redK[r * HK + tid];
        ksum[tid] = s;
    } else if (tid < HK + TP) {
        int p = tid - HK;
        float s = 0.f;
        #pragma unroll
        for (int r = 0; r < 16; r++) s += redX[r * TP + p];
        xsum[p] = s;
    }
    __syncthreads();

    // ---- min-sum main loop: each thread 2 keys x 4 points ----
    const int kg = tid & 63;    // keys  [kg*2, kg*2+2)
    const int pg = tid >> 6;    // points[pg*4, pg*4+4)
    const float* kp = keysT + kg * 2;
    const float* xp = xT + pg * 4;

    float a00 = 0.f, a01 = 0.f, a02 = 0.f, a03 = 0.f;
    float a10 = 0.f, a11 = 0.f, a12 = 0.f, a13 = 0.f;

    #pragma unroll 4
    for (int f = 0; f < Fdim; f++) {
        float2 kv = *(const float2*)(kp + f * KS);       // 2-phase LDS.64
        float4 xv = *(const float4*)(xp + f * XS);       // broadcast LDS.128
        a00 += fminf(kv.x, xv.x);  a10 += fminf(kv.y, xv.x);
        a01 += fminf(kv.x, xv.y);  a11 += fminf(kv.y, xv.y);
        a02 += fminf(kv.x, xv.z);  a12 += fminf(kv.y, xv.z);
        a03 += fminf(kv.x, xv.w);  a13 += fminf(kv.y, xv.w);
    }

    // ---- student-t (TAU=1): t = 1/(1+d^2), float2 stores into tS[p][k] ----
    {
        float k0 = ksum[kg * 2 + 0], k1 = ksum[kg * 2 + 1];
        float acc0[4] = {a00, a01, a02, a03};
        float acc1[4] = {a10, a11, a12, a13};
        #pragma unroll
        for (int j = 0; j < 4; j++) {
            int p = pg * 4 + j;
            float xs_ = xsum[p];
            float d0 = k0 + xs_ - 2.f * acc0[j];
            float d1 = k1 + xs_ - 2.f * acc1[j];
            float2 tv;
            tv.x = __fdividef(1.f, fmaf(d0, d0, 1.f));
            tv.y = __fdividef(1.f, fmaf(d1, d1, 1.f));
            *(float2*)(tS + p * TSs + kg * 2) = tv;
        }
    }
    __syncthreads();

    // ---- per-point: head-normalize + conv + softmax (8 lanes per point) ----
    if (tid < TP * 8) {
        int p = tid >> 3;
        int l = tid & 7;          // lane within 8-lane group; k slice l*4..+4
        float* row = tS + p * TSs;
        float4 t0 = *(float4*)(row +  0 + l * 4);
        float4 t1 = *(float4*)(row + 32 + l * 4);
        float4 t2 = *(float4*)(row + 64 + l * 4);
        float4 t3 = *(float4*)(row + 96 + l * 4);

        float h0 = t0.x + t0.y + t0.z + t0.w;
        float h1 = t1.x + t1.y + t1.z + t1.w;
        float h2 = t2.x + t2.y + t2.z + t2.w;
        float h3 = t3.x + t3.y + t3.z + t3.w;
        #pragma unroll
        for (int m = 1; m < 8; m <<= 1) {
            h0 += __shfl_xor_sync(0xffffffffu, h0, m);
            h1 += __shfl_xor_sync(0xffffffffu, h1, m);
            h2 += __shfl_xor_sync(0xffffffffu, h2, m);
            h3 += __shfl_xor_sync(0xffffffffu, h3, m);
        }
        float w0 = __fdividef(cw[0], h0);
        float w1 = __fdividef(cw[1], h1);
        float w2 = __fdividef(cw[2], h2);
        float w3 = __fdividef(cw[3], h3);

        float C0 = t0.x * w0 + t1.x * w1 + t2.x * w2 + t3.x * w3;
        float C1 = t0.y * w0 + t1.y * w1 + t2.y * w2 + t3.y * w3;
        float C2 = t0.z * w0 + t1.z * w1 + t2.z * w2 + t3.z * w3;
        float C3 = t0.w * w0 + t1.w * w1 + t2.w * w2 + t3.w * w3;

        float mx = fmaxf(fmaxf(C0, C1), fmaxf(C2, C3));
        #pragma unroll
        for (int m = 1; m < 8; m <<= 1)
            mx = fmaxf(mx, __shfl_xor_sync(0xffffffffu, mx, m));

        float e0 = __expf(C0 - mx), e1 = __expf(C1 - mx);
        float e2 = __expf(C2 - mx), e3 = __expf(C3 - mx);
        float s = e0 + e1 + e2 + e3;
        #pragma unroll
        for (int m = 1; m < 8; m <<= 1)
            s += __shfl_xor_sync(0xffffffffu, s, m);
        float inv = __fdividef(1.f, s);

        float4 Sv = make_float4(e0 * inv, e1 * inv, e2 * inv, e3 * inv);
        *(float4*)(row + l * 4) = Sv;                             // S into tS[p][0..32)
        *(float4*)(Sg + (size_t)(p0 + p) * Kk + l * 4) = Sv;      // coalesced S out
    }
    __syncthreads();

    // ---- partial pooling: g_part[blk][k][f] = sum_p S[p][k] * x[p][f] ----
    {
        int f4 = tid & 31;        // f = f4*4
        int kk = tid >> 5;        // k (warp-uniform -> S broadcast)
        const float4* xg = (const float4*)(x + (size_t)p0 * Fdim) + f4;
        float pa0 = 0.f, pa1 = 0.f, pa2 = 0.f, pa3 = 0.f;
        #pragma unroll 4
        for (int n = 0; n < TP; n++) {
            float sv = tS[n * TSs + kk];
            float4 xv = xg[n * 32];
            pa0 = fmaf(sv, xv.x, pa0);
            pa1 = fmaf(sv, xv.y, pa1);
            pa2 = fmaf(sv, xv.z, pa2);
            pa3 = fmaf(sv, xv.w, pa3);
        }
        *(float4*)&g_part[((size_t)blockIdx.x * Kk + kk) * Fdim + f4 * 4] =
            make_float4(pa0, pa1, pa2, pa3);
    }
}

// ---------------------------------------------------------------------------
// Kernel B: reduce 16 partials per row + linear + LeakyReLU.
// Grid 256 (one row = b*32+k), 128 threads (tid = f for reduce, fo for GEMV).
// ---------------------------------------------------------------------------
__global__ __launch_bounds__(128) void out_kernel(
    const float* __restrict__ linw, float* __restrict__ out)
{
    const int row = blockIdx.x;           // b*32 + k
    const int b   = row >> 5;
    const int k   = row & 31;
    const int tid = threadIdx.x;
    __shared__ float pr[Fdim];

    float s = 0.f;
    #pragma unroll
    for (int c = 0; c < 16; c++)
        s += g_part[((size_t)(b * 16 + c) * Kk + k) * Fdim + tid];
    pr[tid] = s;
    __syncthreads();

    const float4* lw = (const float4*)(linw + (size_t)tid * Fdim);  // row fo=tid
    const float4* p4 = (const float4*)pr;
    float a0 = 0.f, a1 = 0.f;
    #pragma unroll
    for (int i = 0; i < 32; i += 2) {
        float4 w0 = lw[i],     v0 = p4[i];
        float4 w1 = lw[i + 1], v1 = p4[i + 1];
        a0 += w0.x * v0.x + w0.y * v0.y + w0.z * v0.z + w0.w * v0.w;
        a1 += w1.x * v1.x + w1.y * v1.y + w1.z * v1.z + w1.w * v1.w;
    }
    float a = a0 + a1;
    out[(size_t)row * FOUT + tid] = (a >= 0.f) ? a : 0.01f * a;
}

// ---------------------------------------------------------------------------
extern "C" void kernel_launch(void* const* d_in, const int* in_sizes, int n_in,
                              void* d_out, int out_size)
{
    const float* x     = (const float*)d_in[0];   // [8,1024,128]
    const float* keys  = (const float*)d_in[1];   // [4,32,128]
    const float* convw = (const float*)d_in[2];   // [4]
    const float* linw  = (const float*)d_in[3];   // [128,128]
    float* out = (float*)d_out;                   // [8,32,128]
    float* Sg  = out + OUT_ELEMS;                 // [8192,32]

    const int smemA = (Fdim * KS + Fdim * XS + TP * TSs
                       + 8 * HK + 16 * TP + HK + TP + 8) * (int)sizeof(float);
    cudaFuncSetAttribute(distS_kernel,
                         cudaFuncAttributeMaxDynamicSharedMemorySize, smemA);

    distS_kernel<<<NBLK, 1024, smemA>>>(x, keys, convw, Sg);
    out_kernel<<<Bb * Kk, 128>>>(linw, out);
}

// round 4
// speedup vs baseline: 1.1298x; 1.1298x over previous
#include <cuda_runtime.h>

// Shapes (fixed)
#define Bb 8
#define Nn 1024
#define BN 8192
#define Fdim 128
#define Hh 4
#define Kk 32
#define HK 128
#define FOUT 128
#define TP 32            // points per block
#define NBLK (BN/TP)     // 256 blocks

#define KS 132           // keysT row stride [f][k]
#define XS 36            // xT row stride [f][p]
#define TSs 132          // tS row stride [p][k]
#define SCR (32*132)     // scratch tile floats (aliased: native stage / tS)

#define OUT_ELEMS (Bb*Kk*FOUT)

__device__ float g_part[NBLK * Kk * Fdim];   // [blk][k][f]
__device__ float g_linT[Fdim * FOUT];        // [f][fo]

// ---------------------------------------------------------------------------
// distS: L1 dist (min-sum) + student-t + head-normalize + conv + softmax +
// partial pooling. 256 blocks x 512 threads, ~108KB smem, 2 CTAs/SM.
// ---------------------------------------------------------------------------
__global__ __launch_bounds__(512, 2) void distS_kernel(
    const float* __restrict__ x, const float* __restrict__ keys,
    const float* __restrict__ convw, const float* __restrict__ linw,
    float* __restrict__ Sg)
{
    extern __shared__ float sm[];
    float* keysT = sm;                    // [128][KS]
    float* xT    = keysT + Fdim * KS;     // [128][XS]
    float* scr   = xT + Fdim * XS;        // [SCR] native stage, later tS[p][k]
    float* redK  = scr + SCR;             // [4][128]
    float* redX  = redK + 4 * HK;         // [16][32]
    float* ksum  = redX + 16 * TP;        // [128]
    float* xsum  = ksum + HK;             // [32]
    float* cw    = xsum + TP;             // [8]

    const int tid = threadIdx.x;
    const int bid = blockIdx.x;
    const int p0  = bid * TP;

    if (tid < Hh) cw[tid] = convw[tid];
    // side-write transposed lin_w (blocks 0..127, one row each; tiny)
    if (bid < FOUT && tid < Fdim)
        g_linT[tid * FOUT + bid] = linw[bid * Fdim + tid];

    // ---- keys transpose, 4 chunks of 32 rows, conflict-free two-stage ----
    const float4* kg4 = (const float4*)keys;
    #pragma unroll
    for (int c = 0; c < 4; c++) {
        #pragma unroll
        for (int it = 0; it < 2; it++) {           // stage 1: native into scr
            int i4 = tid + it * 512;               // 1024 float4
            int kk = i4 >> 5, f4 = i4 & 31;
            float4 v = kg4[(c * 32 + kk) * 32 + f4];
            *(float4*)(scr + kk * 132 + f4 * 4) = v;   // STS.128 conflict-free
        }
        __syncthreads();
        #pragma unroll
        for (int it = 0; it < 2; it++) {           // stage 2: gather k, STS.128
            int i = tid + it * 512;                // 1024 tasks
            int f = i & 127, k4 = i >> 7;          // k4 0..7
            float4 v;
            v.x = scr[(4 * k4 + 0) * 132 + f];     // stride-1 lanes, cf
            v.y = scr[(4 * k4 + 1) * 132 + f];
            v.z = scr[(4 * k4 + 2) * 132 + f];
            v.w = scr[(4 * k4 + 3) * 132 + f];
            *(float4*)(keysT + f * KS + c * 32 + k4 * 4) = v;
        }
        __syncthreads();
    }

    // ---- x tile transpose (same two-stage) ----
    const float4* xg4 = (const float4*)(x + (size_t)p0 * Fdim);
    #pragma unroll
    for (int it = 0; it < 2; it++) {
        int i4 = tid + it * 512;                   // 1024 float4
        int p = i4 >> 5, f4 = i4 & 31;
        float4 v = xg4[i4];
        *(float4*)(scr + p * 132 + f4 * 4) = v;
    }
    __syncthreads();
    #pragma unroll
    for (int it = 0; it < 2; it++) {
        int i = tid + it * 512;
        int f = i & 127, p4 = i >> 7;              // p4 0..7
        float4 v;
        v.x = scr[(4 * p4 + 0) * 132 + f];
        v.y = scr[(4 * p4 + 1) * 132 + f];
        v.z = scr[(4 * p4 + 2) * 132 + f];
        v.w = scr[(4 * p4 + 3) * 132 + f];
        *(float4*)(xT + f * XS + p4 * 4) = v;
    }
    __syncthreads();

    // ---- row sums ----
    {
        int k = tid & 127, part = tid >> 7;        // 4 parts x 32 f
        float s = 0.f;
        #pragma unroll
        for (int i = 0; i < 32; i++) s += keysT[(part * 32 + i) * KS + k];
        redK[part * HK + k] = s;
    }
    {
        int p = tid & 31, part = tid >> 5;         // 16 parts x 8 f
        float s = 0.f;
        #pragma unroll
        for (int i = 0; i < 8; i++) s += xT[(part * 8 + i) * XS + p];
        redX[part * TP + p] = s;
    }
    __syncthreads();
    if (tid < HK) {
        float s = 0.f;
        #pragma unroll
        for (int r = 0; r < 4; r++) s += redK[r * HK + tid];
        ksum[tid] = s;
    } else if (tid < HK + TP) {
        int p = tid - HK;
        float s = 0.f;
        #pragma unroll
        for (int r = 0; r < 16; r++) s += redX[r * TP + p];
        xsum[p] = s;
    }
    __syncthreads();

    // ---- min-sum main loop: 4 keys x 2 points per thread ----
    const int kg = tid & 31;    // keys  [kg*4, kg*4+4)
    const int pg = tid >> 5;    // points[pg*2, pg*2+2)
    const float* kp = keysT + kg * 4;
    const float* xp = xT + pg * 2;

    float a00 = 0.f, a10 = 0.f, a20 = 0.f, a30 = 0.f;
    float a01 = 0.f, a11 = 0.f, a21 = 0.f, a31 = 0.f;

    #pragma unroll 4
    for (int f = 0; f < Fdim; f++) {
        float4 kv = *(const float4*)(kp + f * KS);   // 16B lane-stride, cf
        float2 xv = *(const float2*)(xp + f * XS);   // broadcast
        a00 += fminf(kv.x, xv.x);  a01 += fminf(kv.x, xv.y);
        a10 += fminf(kv.y, xv.x);  a11 += fminf(kv.y, xv.y);
        a20 += fminf(kv.z, xv.x);  a21 += fminf(kv.z, xv.y);
        a30 += fminf(kv.w, xv.x);  a31 += fminf(kv.w, xv.y);
    }

    // ---- student-t (TAU=1): t = 1/(1+d^2) into scr as tS[p][k] ----
    {
        float4 kv = *(const float4*)(ksum + kg * 4);
        float x0 = xsum[pg * 2 + 0], x1 = xsum[pg * 2 + 1];
        float4 t0, t1;
        float d;
        d = kv.x + x0 - 2.f * a00; t0.x = __fdividef(1.f, fmaf(d, d, 1.f));
        d = kv.y + x0 - 2.f * a10; t0.y = __fdividef(1.f, fmaf(d, d, 1.f));
        d = kv.z + x0 - 2.f * a20; t0.z = __fdividef(1.f, fmaf(d, d, 1.f));
        d = kv.w + x0 - 2.f * a30; t0.w = __fdividef(1.f, fmaf(d, d, 1.f));
        d = kv.x + x1 - 2.f * a01; t1.x = __fdividef(1.f, fmaf(d, d, 1.f));
        d = kv.y + x1 - 2.f * a11; t1.y = __fdividef(1.f, fmaf(d, d, 1.f));
        d = kv.z + x1 - 2.f * a21; t1.z = __fdividef(1.f, fmaf(d, d, 1.f));
        d = kv.w + x1 - 2.f * a31; t1.w = __fdividef(1.f, fmaf(d, d, 1.f));
        *(float4*)(scr + (pg * 2 + 0) * TSs + kg * 4) = t0;
        *(float4*)(scr + (pg * 2 + 1) * TSs + kg * 4) = t1;
    }
    __syncthreads();

    // ---- per-point: head-normalize + conv + softmax (8 lanes / point) ----
    if (tid < TP * 8) {
        int p = tid >> 3;
        int l = tid & 7;
        float* row = scr + p * TSs;
        float4 t0 = *(float4*)(row +  0 + l * 4);
        float4 t1 = *(float4*)(row + 32 + l * 4);
        float4 t2 = *(float4*)(row + 64 + l * 4);
        float4 t3 = *(float4*)(row + 96 + l * 4);

        float h0 = t0.x + t0.y + t0.z + t0.w;
        float h1 = t1.x + t1.y + t1.z + t1.w;
        float h2 = t2.x + t2.y + t2.z + t2.w;
        float h3 = t3.x + t3.y + t3.z + t3.w;
        #pragma unroll
        for (int m = 1; m < 8; m <<= 1) {
            h0 += __shfl_xor_sync(0xffffffffu, h0, m);
            h1 += __shfl_xor_sync(0xffffffffu, h1, m);
            h2 += __shfl_xor_sync(0xffffffffu, h2, m);
            h3 += __shfl_xor_sync(0xffffffffu, h3, m);
        }
        float w0 = __fdividef(cw[0], h0);
        float w1 = __fdividef(cw[1], h1);
        float w2 = __fdividef(cw[2], h2);
        float w3 = __fdividef(cw[3], h3);

        float C0 = t0.x * w0 + t1.x * w1 + t2.x * w2 + t3.x * w3;
        float C1 = t0.y * w0 + t1.y * w1 + t2.y * w2 + t3.y * w3;
        float C2 = t0.z * w0 + t1.z * w1 + t2.z * w2 + t3.z * w3;
        float C3 = t0.w * w0 + t1.w * w1 + t2.w * w2 + t3.w * w3;

        float mx = fmaxf(fmaxf(C0, C1), fmaxf(C2, C3));
        #pragma unroll
        for (int m = 1; m < 8; m <<= 1)
            mx = fmaxf(mx, __shfl_xor_sync(0xffffffffu, mx, m));

        float e0 = __expf(C0 - mx), e1 = __expf(C1 - mx);
        float e2 = __expf(C2 - mx), e3 = __expf(C3 - mx);
        float s = e0 + e1 + e2 + e3;
        #pragma unroll
        for (int m = 1; m < 8; m <<= 1)
            s += __shfl_xor_sync(0xffffffffu, s, m);
        float inv = __fdividef(1.f, s);

        float4 Sv = make_float4(e0 * inv, e1 * inv, e2 * inv, e3 * inv);
        *(float4*)(row + l * 4) = Sv;
        *(float4*)(Sg + (size_t)(p0 + p) * Kk + l * 4) = Sv;
    }
    __syncthreads();

    // ---- partial pooling: g_part[bid][k][f] = sum_p S[p][k] * x[p][f] ----
    {
        int k  = tid >> 4;          // 32 k
        int f4 = tid & 15;          // f chunks f4 and f4+16
        const float4* xg = (const float4*)(x + (size_t)p0 * Fdim);
        float4 A = make_float4(0.f, 0.f, 0.f, 0.f);
        float4 B = make_float4(0.f, 0.f, 0.f, 0.f);
        #pragma unroll 4
        for (int n = 0; n < TP; n++) {
            float sv  = scr[n * TSs + k];
            float4 v0 = xg[n * 32 + f4];
            float4 v1 = xg[n * 32 + f4 + 16];
            A.x = fmaf(sv, v0.x, A.x); A.y = fmaf(sv, v0.y, A.y);
            A.z = fmaf(sv, v0.z, A.z); A.w = fmaf(sv, v0.w, A.w);
            B.x = fmaf(sv, v1.x, B.x); B.y = fmaf(sv, v1.y, B.y);
            B.z = fmaf(sv, v1.z, B.z); B.w = fmaf(sv, v1.w, B.w);
        }
        float* dst = &g_part[((size_t)bid * Kk + k) * Fdim];
        *(float4*)(dst + f4 * 4)        = A;
        *(float4*)(dst + (f4 + 16) * 4) = B;
    }
}

// ---------------------------------------------------------------------------
// out: reduce 32 partials per row + linear (coalesced g_linT) + LeakyReLU.
// ---------------------------------------------------------------------------
__global__ __launch_bounds__(128) void out_kernel(float* __restrict__ out)
{
    const int row = blockIdx.x;           // b*32 + k
    const int b   = row >> 5;
    const int k   = row & 31;
    const int tid = threadIdx.x;
    __shared__ float pr[Fdim];

    float s = 0.f;
    #pragma unroll
    for (int c = 0; c < 32; c++)
        s += g_part[((size_t)(b * 32 + c) * Kk + k) * Fdim + tid];
    pr[tid] = s;
    __syncthreads();

    float a = 0.f;
    #pragma unroll
    for (int f = 0; f < Fdim; f++)
        a += pr[f] * g_linT[f * FOUT + tid];   // coalesced, L2-resident

    out[(size_t)row * FOUT + tid] = (a >= 0.f) ? a : 0.01f * a;
}

// ---------------------------------------------------------------------------
extern "C" void kernel_launch(void* const* d_in, const int* in_sizes, int n_in,
                              void* d_out, int out_size)
{
    const float* x     = (const float*)d_in[0];
    const float* keys  = (const float*)d_in[1];
    const float* convw = (const float*)d_in[2];
    const float* linw  = (const float*)d_in[3];
    float* out = (float*)d_out;                   // [8,32,128]
    float* Sg  = out + OUT_ELEMS;                 // [8192,32]

    const int smemA = (Fdim * KS + Fdim * XS + SCR
                       + 4 * HK + 16 * TP + HK + TP + 8) * (int)sizeof(float);
    cudaFuncSetAttribute(distS_kernel,
                         cudaFuncAttributeMaxDynamicSharedMemorySize, smemA);

    distS_kernel<<<NBLK, 512, smemA>>>(x, keys, convw, linw, Sg);
    out_kernel<<<Bb * Kk, 128>>>(out);
}

// round 5
// speedup vs baseline: 1.3434x; 1.1891x over previous
#include <cuda_runtime.h>

// Shapes (fixed)
#define Bb 8
#define Nn 1024
#define BN 8192
#define Fdim 128
#define Hh 4
#define Kk 32
#define HK 128
#define FOUT 128
#define TP 64            // points per block
#define NBLK (BN/TP)     // 128 blocks

#define KS 132           // keysT row stride [f][k]
#define XS 68            // xT row stride [f][p]
#define TSs 132          // tS row stride [p][k]
#define SCRN (TP*TSs)    // 8448 floats (staging / tS alias)

#define OUT_ELEMS (Bb*Kk*FOUT)

__device__ float g_part[NBLK * Kk * Fdim];   // [blk][k][f]  (2MB)
__device__ float g_linT[Fdim * FOUT];        // [f][fo]

// ---------------------------------------------------------------------------
// distS: L1 dist (min-sum) + student-t + head-normalize + conv + softmax +
// partial pooling. 128 blocks x 512 threads, ~137KB smem, 1 CTA/SM.
// ---------------------------------------------------------------------------
__global__ __launch_bounds__(512, 1) void distS_kernel(
    const float* __restrict__ x, const float* __restrict__ keys,
    const float* __restrict__ convw, const float* __restrict__ linw,
    float* __restrict__ Sg)
{
    extern __shared__ float sm[];
    float* keysT = sm;                    // [128][KS]
    float* xT    = keysT + Fdim * KS;     // [128][XS]
    float* scr   = xT + Fdim * XS;        // [SCRN] staging -> redK/redX -> tS
    float* ksum  = scr + SCRN;            // [128]
    float* xsum  = ksum + HK;             // [64]
    float* cw    = xsum + TP;             // [8]

    float* redK = scr;                    // [4][128]  (aliased, pre-tS)
    float* redX = scr + 512;              // [8][64]

    const int tid = threadIdx.x;
    const int bid = blockIdx.x;
    const int p0  = bid * TP;

    if (tid < Hh) cw[tid] = convw[tid];
    // side-write transposed lin_w (each of 128 blocks does one row)
    if (tid < Fdim)
        g_linT[tid * FOUT + bid] = linw[bid * Fdim + tid];

    // ---- keys transpose, 4 chunks of 32 rows, conflict-free two-stage ----
    const float4* kg4 = (const float4*)keys;
    #pragma unroll
    for (int c = 0; c < 4; c++) {
        #pragma unroll
        for (int it = 0; it < 2; it++) {           // stage 1: native into scr
            int i4 = tid + it * 512;               // 1024 float4
            int kk = i4 >> 5, f4 = i4 & 31;
            float4 v = kg4[(c * 32 + kk) * 32 + f4];
            *(float4*)(scr + kk * 132 + f4 * 4) = v;
        }
        __syncthreads();
        #pragma unroll
        for (int it = 0; it < 2; it++) {           // stage 2: gather k, STS.128
            int i = tid + it * 512;
            int f = i & 127, k4 = i >> 7;          // k4 0..7
            float4 v;
            v.x = scr[(4 * k4 + 0) * 132 + f];
            v.y = scr[(4 * k4 + 1) * 132 + f];
            v.z = scr[(4 * k4 + 2) * 132 + f];
            v.w = scr[(4 * k4 + 3) * 132 + f];
            *(float4*)(keysT + f * KS + c * 32 + k4 * 4) = v;
        }
        __syncthreads();
    }

    // ---- x tile transpose: 2 chunks of 32 rows ----
    const float4* xg4 = (const float4*)(x + (size_t)p0 * Fdim);
    #pragma unroll
    for (int c = 0; c < 2; c++) {
        #pragma unroll
        for (int it = 0; it < 2; it++) {
            int i4 = tid + it * 512;               // 1024 float4
            int p = i4 >> 5, f4 = i4 & 31;
            float4 v = xg4[(c * 32 + p) * 32 + f4];
            *(float4*)(scr + p * 132 + f4 * 4) = v;
        }
        __syncthreads();
        #pragma unroll
        for (int it = 0; it < 2; it++) {
            int i = tid + it * 512;
            int f = i & 127, p4 = i >> 7;          // p4 0..7
            float4 v;
            v.x = scr[(4 * p4 + 0) * 132 + f];
            v.y = scr[(4 * p4 + 1) * 132 + f];
            v.z = scr[(4 * p4 + 2) * 132 + f];
            v.w = scr[(4 * p4 + 3) * 132 + f];
            *(float4*)(xT + f * XS + c * 32 + p4 * 4) = v;
        }
        __syncthreads();
    }

    // ---- row sums (redK/redX alias scr; tS not yet live) ----
    {
        int k = tid & 127, part = tid >> 7;        // 4 parts x 32 f
        float s = 0.f;
        #pragma unroll
        for (int i = 0; i < 32; i++) s += keysT[(part * 32 + i) * KS + k];
        redK[part * HK + k] = s;
    }
    __syncthreads();
    {
        int p = tid & 63, part = tid >> 6;         // 8 parts x 16 f
        float s = 0.f;
        #pragma unroll
        for (int i = 0; i < 16; i++) s += xT[(part * 16 + i) * XS + p];
        redX[part * TP + p] = s;
    }
    __syncthreads();
    if (tid < HK) {
        float s = 0.f;
        #pragma unroll
        for (int r = 0; r < 4; r++) s += redK[r * HK + tid];
        ksum[tid] = s;
    } else if (tid < HK + TP) {
        int p = tid - HK;
        float s = 0.f;
        #pragma unroll
        for (int r = 0; r < 8; r++) s += redX[r * TP + p];
        xsum[p] = s;
    }
    __syncthreads();

    // ---- min-sum main loop: 4 keys x 4 points per thread ----
    const int kg = tid & 31;    // keys  [kg*4, kg*4+4)
    const int pg = tid >> 5;    // points[pg*4, pg*4+4)  (warp-uniform)
    const float* kp = keysT + kg * 4;
    const float* xp = xT + pg * 4;

    float a[4][4];
    #pragma unroll
    for (int i = 0; i < 4; i++)
        #pragma unroll
        for (int j = 0; j < 4; j++) a[i][j] = 0.f;

    #pragma unroll 4
    for (int f = 0; f < Fdim; f++) {
        float4 kv = *(const float4*)(kp + f * KS);   // 16B lane-stride, cf
        float4 xv = *(const float4*)(xp + f * XS);   // broadcast
        float kf[4] = {kv.x, kv.y, kv.z, kv.w};
        float xf[4] = {xv.x, xv.y, xv.z, xv.w};
        #pragma unroll
        for (int i = 0; i < 4; i++)
            #pragma unroll
            for (int j = 0; j < 4; j++)
                a[i][j] += fminf(kf[i], xf[j]);
    }

    // ---- student-t (TAU=1): t = 1/(1+d^2) into scr as tS[p][k] ----
    {
        float4 kv = *(const float4*)(ksum + kg * 4);
        float kf[4] = {kv.x, kv.y, kv.z, kv.w};
        #pragma unroll
        for (int j = 0; j < 4; j++) {
            int p = pg * 4 + j;
            float xs_ = xsum[p];
            float4 tv;
            float d;
            d = kf[0] + xs_ - 2.f * a[0][j]; tv.x = __fdividef(1.f, fmaf(d, d, 1.f));
            d = kf[1] + xs_ - 2.f * a[1][j]; tv.y = __fdividef(1.f, fmaf(d, d, 1.f));
            d = kf[2] + xs_ - 2.f * a[2][j]; tv.z = __fdividef(1.f, fmaf(d, d, 1.f));
            d = kf[3] + xs_ - 2.f * a[3][j]; tv.w = __fdividef(1.f, fmaf(d, d, 1.f));
            *(float4*)(scr + p * TSs + kg * 4) = tv;
        }
    }
    __syncthreads();

    // ---- per-point: head-normalize + conv + softmax (8 lanes / point) ----
    {
        int p = tid >> 3;          // 64 points x 8 lanes = 512
        int l = tid & 7;
        float* row = scr + p * TSs;
        float4 t0 = *(float4*)(row +  0 + l * 4);
        float4 t1 = *(float4*)(row + 32 + l * 4);
        float4 t2 = *(float4*)(row + 64 + l * 4);
        float4 t3 = *(float4*)(row + 96 + l * 4);

        float h0 = t0.x + t0.y + t0.z + t0.w;
        float h1 = t1.x + t1.y + t1.z + t1.w;
        float h2 = t2.x + t2.y + t2.z + t2.w;
        float h3 = t3.x + t3.y + t3.z + t3.w;
        #pragma unroll
        for (int m = 1; m < 8; m <<= 1) {
            h0 += __shfl_xor_sync(0xffffffffu, h0, m);
            h1 += __shfl_xor_sync(0xffffffffu, h1, m);
            h2 += __shfl_xor_sync(0xffffffffu, h2, m);
            h3 += __shfl_xor_sync(0xffffffffu, h3, m);
        }
        float w0 = __fdividef(cw[0], h0);
        float w1 = __fdividef(cw[1], h1);
        float w2 = __fdividef(cw[2], h2);
        float w3 = __fdividef(cw[3], h3);

        float C0 = t0.x * w0 + t1.x * w1 + t2.x * w2 + t3.x * w3;
        float C1 = t0.y * w0 + t1.y * w1 + t2.y * w2 + t3.y * w3;
        float C2 = t0.z * w0 + t1.z * w1 + t2.z * w2 + t3.z * w3;
        float C3 = t0.w * w0 + t1.w * w1 + t2.w * w2 + t3.w * w3;

        float mx = fmaxf(fmaxf(C0, C1), fmaxf(C2, C3));
        #pragma unroll
        for (int m = 1; m < 8; m <<= 1)
            mx = fmaxf(mx, __shfl_xor_sync(0xffffffffu, mx, m));

        float e0 = __expf(C0 - mx), e1 = __expf(C1 - mx);
        float e2 = __expf(C2 - mx), e3 = __expf(C3 - mx);
        float s = e0 + e1 + e2 + e3;
        #pragma unroll
        for (int m = 1; m < 8; m <<= 1)
            s += __shfl_xor_sync(0xffffffffu, s, m);
        float inv = __fdividef(1.f, s);

        float4 Sv = make_float4(e0 * inv, e1 * inv, e2 * inv, e3 * inv);
        *(float4*)(row + l * 4) = Sv;
        *(float4*)(Sg + (size_t)(p0 + p) * Kk + l * 4) = Sv;
    }
    __syncthreads();

    // ---- partial pooling: g_part[bid][k][f] = sum_p S[p][k] * x[p][f] ----
    {
        int k  = tid >> 4;          // 32 k (2 distinct per warp -> broadcast)
        int f4 = tid & 15;          // f chunks f4 and f4+16
        const float4* xg = (const float4*)(x + (size_t)p0 * Fdim);
        float4 A = make_float4(0.f, 0.f, 0.f, 0.f);
        float4 B = make_float4(0.f, 0.f, 0.f, 0.f);
        #pragma unroll 4
        for (int n = 0; n < TP; n++) {
            float sv  = scr[n * TSs + k];
            float4 v0 = xg[n * 32 + f4];
            float4 v1 = xg[n * 32 + f4 + 16];
            A.x = fmaf(sv, v0.x, A.x); A.y = fmaf(sv, v0.y, A.y);
            A.z = fmaf(sv, v0.z, A.z); A.w = fmaf(sv, v0.w, A.w);
            B.x = fmaf(sv, v1.x, B.x); B.y = fmaf(sv, v1.y, B.y);
            B.z = fmaf(sv, v1.z, B.z); B.w = fmaf(sv, v1.w, B.w);
        }
        float* dst = &g_part[((size_t)bid * Kk + k) * Fdim];
        *(float4*)(dst + f4 * 4)        = A;
        *(float4*)(dst + (f4 + 16) * 4) = B;
    }
}

// ---------------------------------------------------------------------------
// out: reduce 16 partials per row + linear + LeakyReLU.
// 256 blocks (row = b*32+k) x 512 threads.
// ---------------------------------------------------------------------------
__global__ __launch_bounds__(512) void out_kernel(float* __restrict__ out)
{
    const int row = blockIdx.x;           // b*32 + k
    const int b   = row >> 5;
    const int k   = row & 31;
    const int tid = threadIdx.x;
    __shared__ float red[4 * Fdim];
    __shared__ float pr[Fdim];

    // stage 1: 4 c-groups x 128 f; each thread sums 4 partials (independent)
    {
        int c4 = tid >> 7;                 // 0..3
        int f  = tid & 127;
        float s = 0.f;
        #pragma unroll
        for (int i = 0; i < 4; i++) {
            int blk = b * 16 + c4 * 4 + i;         // distS block index
            s += g_part[((size_t)blk * Kk + k) * Fdim + f];
        }
        red[c4 * Fdim + f] = s;
    }
    __syncthreads();
    if (tid < Fdim)
        pr[tid] = red[tid] + red[Fdim + tid] + red[2 * Fdim + tid]
                + red[3 * Fdim + tid];
    __syncthreads();

    // stage 2: GEMV, 4 threads per fo (split f range), coalesced g_linT
    {
        int fo = tid & 127;
        int q  = tid >> 7;                 // f in [q*32, q*32+32)
        float a = 0.f;
        #pragma unroll
        for (int i = 0; i < 32; i++) {
            int f = q * 32 + i;
            a += pr[f] * g_linT[f * FOUT + fo];
        }
        red[q * Fdim + fo] = a;
    }
    __syncthreads();
    if (tid < Fdim) {
        float a = red[tid] + red[Fdim + tid] + red[2 * Fdim + tid]
                + red[3 * Fdim + tid];
        out[(size_t)row * FOUT + tid] = (a >= 0.f) ? a : 0.01f * a;
    }
}

// ---------------------------------------------------------------------------
extern "C" void kernel_launch(void* const* d_in, const int* in_sizes, int n_in,
                              void* d_out, int out_size)
{
    const float* x     = (const float*)d_in[0];
    const float* keys  = (const float*)d_in[1];
    const float* convw = (const float*)d_in[2];
    const float* linw  = (const float*)d_in[3];
    float* out = (float*)d_out;                   // [8,32,128]
    float* Sg  = out + OUT_ELEMS;                 // [8192,32]

    const int smemA = (Fdim * KS + Fdim * XS + SCRN + HK + TP + 8)
                      * (int)sizeof(float);
    cudaFuncSetAttribute(distS_kernel,
                         cudaFuncAttributeMaxDynamicSharedMemorySize, smemA);

    distS_kernel<<<NBLK, 512, smemA>>>(x, keys, convw, linw, Sg);
    out_kernel<<<Bb * Kk, 512>>>(out);
}